// round 2
// baseline (speedup 1.0000x reference)
#include <cuda_runtime.h>
#include <cstdint>

// Problem shape (fixed by the dataset): predictions/target are [1024, 8192] fp32.
#define BB 1024
#define NN 8192
#define KK 10
#define THREADS 256
#define NWARP (THREADS / 32)
#define F4_PER_ROW (NN / 4)          // 2048
#define ITERS (F4_PER_ROW / THREADS) // 8

// Per-row partial losses (static device global: no allocation).
__device__ float g_partial[BB];

__device__ __forceinline__ unsigned long long umax64(unsigned long long a,
                                                     unsigned long long b) {
    return a > b ? a : b;
}

// Pack (value, index) into a 64-bit key:
//   key = ((fbits + 1) << 13) | (NN-1 - idx)
// Monotone in target value (targets >= 0 so float bits order as uint),
// larger key = larger value; on equal value, larger key = smaller index
// (matches stable argsort(-target)). All real keys > 0 and globally unique.
__device__ __forceinline__ unsigned long long pack_key(float v, int idx) {
    unsigned int fb = __float_as_uint(v);
    return (((unsigned long long)fb + 1ull) << 13) |
           (unsigned long long)(NN - 1 - idx);
}

__global__ __launch_bounds__(THREADS)
void vml_row_kernel(const float* __restrict__ pred,
                    const float* __restrict__ targ) {
    const int row = blockIdx.x;
    const int tid = threadIdx.x;
    const int lane = tid & 31;
    const int warp = tid >> 5;

    const float4* t4 = reinterpret_cast<const float4*>(targ + (size_t)row * NN);
    const float4* p4 = reinterpret_cast<const float4*>(pred + (size_t)row * NN);
    const float* pred_row = pred + (size_t)row * NN;

    __shared__ unsigned long long s_warp_top[NWARP * KK]; // 80 keys
    __shared__ float s_t[KK];
    __shared__ int   s_i[KK];
    __shared__ float s_p[KK];
    __shared__ float s_c[KK];
    __shared__ float s_sums[NWARP][KK];
    __shared__ float s_loss[KK];

    // ---------------- Phase A: per-thread top-10 of target ----------------
    unsigned long long v[KK];
#pragma unroll
    for (int i = 0; i < KK; i++) v[i] = 0ull;

#pragma unroll
    for (int it = 0; it < ITERS; it++) {
        const int f4i = tid + it * THREADS;
        float4 t = t4[f4i];
        const int base = f4i * 4;
        float vals[4] = {t.x, t.y, t.z, t.w};
#pragma unroll
        for (int e = 0; e < 4; e++) {
            unsigned long long key = pack_key(vals[e], base + e);
            if (key > v[KK - 1]) {
                v[KK - 1] = key;
#pragma unroll
                for (int i = KK - 1; i > 0; i--) {
                    if (v[i] > v[i - 1]) {
                        unsigned long long tmp = v[i - 1];
                        v[i - 1] = v[i];
                        v[i] = tmp;
                    }
                }
            }
        }
    }

    // Warp-level 32-way merge by heads: 10 rounds of warp argmax; keys are
    // unique so exactly one lane matches the max and pops its head.
    {
        unsigned long long head = v[0];
#pragma unroll
        for (int r = 0; r < KK; r++) {
            unsigned long long m = head;
#pragma unroll
            for (int off = 16; off > 0; off >>= 1)
                m = umax64(m, __shfl_xor_sync(0xffffffffu, m, off));
            if (head == m) {
#pragma unroll
                for (int i = 0; i < KK - 1; i++) v[i] = v[i + 1];
                v[KK - 1] = 0ull;
                head = v[0];
            }
            if (lane == 0) s_warp_top[warp * KK + r] = m;
        }
    }
    __syncthreads();

    // Warp 0: reduce 80 candidate keys -> global top-10 (in rank order).
    if (warp == 0) {
        unsigned long long k0 = s_warp_top[lane];
        unsigned long long k1 = s_warp_top[lane + 32];
        unsigned long long k2 = (lane + 64 < NWARP * KK) ? s_warp_top[lane + 64] : 0ull;
#pragma unroll
        for (int r = 0; r < KK; r++) {
            unsigned long long loc = umax64(k0, umax64(k1, k2));
            unsigned long long m = loc;
#pragma unroll
            for (int off = 16; off > 0; off >>= 1)
                m = umax64(m, __shfl_xor_sync(0xffffffffu, m, off));
            if (k0 == m) k0 = 0ull;
            else if (k1 == m) k1 = 0ull;
            else if (k2 == m) k2 = 0ull;
            if (lane == r) {
                unsigned int fb = (unsigned int)(m >> 13) - 1u;
                int idx = (NN - 1) - (int)(m & (unsigned long long)(NN - 1));
                s_t[r] = __uint_as_float(fb);
                s_i[r] = idx;
            }
        }
        __syncwarp();
        // Gather top predictions, build c_k = 0.5*t_k - p_k.
        if (lane < KK) {
            float pk = pred_row[s_i[lane]];
            s_p[lane] = pk;
            s_c[lane] = 0.5f * s_t[lane] - pk;
        }
    }
    __syncthreads();

    // ---------------- Phase B: hinge sums over all predictions ----------------
    float c[KK];
#pragma unroll
    for (int k = 0; k < KK; k++) c[k] = s_c[k];

    float s[KK];
#pragma unroll
    for (int k = 0; k < KK; k++) s[k] = 0.f;

#pragma unroll
    for (int it = 0; it < ITERS; it++) {
        float4 p = p4[tid + it * THREADS];
        float pv[4] = {p.x, p.y, p.z, p.w};
#pragma unroll
        for (int e = 0; e < 4; e++) {
#pragma unroll
            for (int k = 0; k < KK; k++)
                s[k] += fmaxf(c[k] + pv[e], 0.f);
        }
    }

    // Warp reduce each of the 10 sums.
#pragma unroll
    for (int k = 0; k < KK; k++) {
#pragma unroll
        for (int off = 16; off > 0; off >>= 1)
            s[k] += __shfl_xor_sync(0xffffffffu, s[k], off);
    }
    if (lane == 0) {
#pragma unroll
        for (int k = 0; k < KK; k++) s_sums[warp][k] = s[k];
    }
    __syncthreads();

    if (tid < KK) {
        const int k = tid;
        float S = 0.f;
#pragma unroll
        for (int w = 0; w < NWARP; w++) S += s_sums[w][k];
        // Subtract contributions of ranks r <= k (they have rank(j) <= k).
        float ck = s_c[k];
        float sub = 0.f;
        for (int r = 0; r <= k; r++) sub += fmaxf(ck + s_p[r], 0.f);
        float per = (S - sub) / (float)(NN - k);
        s_loss[k] = (s_t[k] > 0.25f) ? per : 0.f;
    }
    __syncthreads();

    if (tid == 0) {
        float acc = 0.f;
#pragma unroll
        for (int k = 0; k < KK; k++) acc += s_loss[k];
        g_partial[row] = acc;
    }
}

// Deterministic final reduction of 1024 per-row partials.
__global__ void vml_reduce_kernel(float* __restrict__ out) {
    __shared__ float sh[BB];
    const int t = threadIdx.x;
    sh[t] = g_partial[t];
    __syncthreads();
#pragma unroll
    for (int stride = BB / 2; stride > 0; stride >>= 1) {
        if (t < stride) sh[t] += sh[t + stride];
        __syncthreads();
    }
    if (t == 0) out[0] = sh[0];
}

extern "C" void kernel_launch(void* const* d_in, const int* in_sizes, int n_in,
                              void* d_out, int out_size) {
    const float* pred = (const float*)d_in[0];
    const float* targ = (const float*)d_in[1];
    vml_row_kernel<<<BB, THREADS>>>(pred, targ);
    vml_reduce_kernel<<<1, BB>>>((float*)d_out);
}

// round 3
// speedup vs baseline: 2.0486x; 2.0486x over previous
#include <cuda_runtime.h>
#include <cstdint>

// Fixed problem shape: predictions/target are [1024, 8192] fp32.
#define BB 1024
#define NN 8192
#define KK 10
#define THREADS 256
#define NWARP (THREADS / 32)
#define ITERS ((NN / 4) / THREADS)   // 8 float4 iters per thread
#define CAP 416                      // candidate buffer (13 per lane of warp 0)
#define FILT_T 0.99f

typedef unsigned long long u64;

// Static device scratch (no allocations allowed).
__device__ float g_partial[BB];
__device__ unsigned int g_ticket;    // zero-init at load; reset by last block

__device__ __forceinline__ u64 umax64(u64 a, u64 b) { return a > b ? a : b; }

// key = ((fbits+1)<<13) | (NN-1-idx): monotone in value (targets >= 0),
// min-index tie-break, all keys > 0 and globally unique per row.
__device__ __forceinline__ u64 pack_key(float v, int idx) {
    return (((u64)__float_as_uint(v) + 1ull) << 13) | (u64)(NN - 1 - idx);
}

__device__ __forceinline__ u64 pack2(float lo, float hi) {
    u64 r; asm("mov.b64 %0, {%1, %2};" : "=l"(r) : "f"(lo), "f"(hi)); return r;
}
__device__ __forceinline__ u64 add2(u64 a, u64 b) {
    u64 r; asm("add.rn.f32x2 %0, %1, %2;" : "=l"(r) : "l"(a), "l"(b)); return r;
}
__device__ __forceinline__ float sum2(u64 a) {
    float x, y; asm("mov.b64 {%0, %1}, %2;" : "=f"(x), "=f"(y) : "l"(a));
    return x + y;
}

__global__ __launch_bounds__(THREADS)
void vml_kernel(const float* __restrict__ pred,
                const float* __restrict__ targ,
                float* __restrict__ out) {
    const int row  = blockIdx.x;
    const int tid  = threadIdx.x;
    const int lane = tid & 31;
    const int warp = tid >> 5;

    const float4* t4 = reinterpret_cast<const float4*>(targ + (size_t)row * NN);
    const float4* p4 = reinterpret_cast<const float4*>(pred + (size_t)row * NN);
    const float* pred_row = pred + (size_t)row * NN;

    __shared__ int  s_count;
    __shared__ u64  s_cand[CAP];
    __shared__ u64  s_warp_top[NWARP * KK];   // fallback only
    __shared__ float s_t[KK];
    __shared__ int   s_i[KK];
    __shared__ float s_p[KK];
    __shared__ float s_c[KK];
    __shared__ float s_sums[NWARP][KK];
    __shared__ float s_sumx[NWARP];
    __shared__ float s_loss[KK];
    __shared__ bool  s_last;

    // ---------------- Phase A: top-10 of target via threshold filter ----------
    if (tid == 0) s_count = 0;
    __syncthreads();

#pragma unroll
    for (int it = 0; it < ITERS; it++) {
        const int f4i = tid + it * THREADS;
        float4 t = t4[f4i];
        const int base = f4i * 4;
        float vals[4] = {t.x, t.y, t.z, t.w};
#pragma unroll
        for (int e = 0; e < 4; e++) {
            if (vals[e] > FILT_T) {
                int p = atomicAdd(&s_count, 1);
                if (p < CAP) s_cand[p] = pack_key(vals[e], base + e);
            }
        }
    }
    __syncthreads();

    const bool filter_ok = (s_count >= KK && s_count <= CAP);

    if (filter_ok) {
        // Warp 0: exact top-10 over <=416 unique candidate keys.
        if (warp == 0) {
            const int cnt = s_count;
            u64 loc[CAP / 32];
#pragma unroll
            for (int i = 0; i < CAP / 32; i++) {
                int ix = lane + i * 32;
                loc[i] = (ix < cnt) ? s_cand[ix] : 0ull;
            }
#pragma unroll
            for (int r = 0; r < KK; r++) {
                u64 lm = loc[0];
#pragma unroll
                for (int i = 1; i < CAP / 32; i++) lm = umax64(lm, loc[i]);
                u64 m = lm;
#pragma unroll
                for (int off = 16; off > 0; off >>= 1)
                    m = umax64(m, __shfl_xor_sync(0xffffffffu, m, off));
#pragma unroll
                for (int i = 0; i < CAP / 32; i++)
                    if (loc[i] == m) loc[i] = 0ull;   // unique: one match total
                if (lane == r) {
                    s_t[r] = __uint_as_float((unsigned)(m >> 13) - 1u);
                    s_i[r] = (NN - 1) - (int)(m & (u64)(NN - 1));
                }
            }
        }
    } else {
        // ---------- Exact fallback (verified round-2 path) ----------
        u64 v[KK];
#pragma unroll
        for (int i = 0; i < KK; i++) v[i] = 0ull;
#pragma unroll
        for (int it = 0; it < ITERS; it++) {
            const int f4i = tid + it * THREADS;
            float4 t = t4[f4i];
            const int base = f4i * 4;
            float vals[4] = {t.x, t.y, t.z, t.w};
#pragma unroll
            for (int e = 0; e < 4; e++) {
                u64 key = pack_key(vals[e], base + e);
                if (key > v[KK - 1]) {
                    v[KK - 1] = key;
#pragma unroll
                    for (int i = KK - 1; i > 0; i--) {
                        if (v[i] > v[i - 1]) { u64 tmp = v[i - 1]; v[i - 1] = v[i]; v[i] = tmp; }
                    }
                }
            }
        }
        {
            u64 head = v[0];
#pragma unroll
            for (int r = 0; r < KK; r++) {
                u64 m = head;
#pragma unroll
                for (int off = 16; off > 0; off >>= 1)
                    m = umax64(m, __shfl_xor_sync(0xffffffffu, m, off));
                if (head == m) {
#pragma unroll
                    for (int i = 0; i < KK - 1; i++) v[i] = v[i + 1];
                    v[KK - 1] = 0ull;
                    head = v[0];
                }
                if (lane == 0) s_warp_top[warp * KK + r] = m;
            }
        }
        __syncthreads();
        if (warp == 0) {
            u64 k0 = s_warp_top[lane];
            u64 k1 = s_warp_top[lane + 32];
            u64 k2 = (lane + 64 < NWARP * KK) ? s_warp_top[lane + 64] : 0ull;
#pragma unroll
            for (int r = 0; r < KK; r++) {
                u64 m = umax64(k0, umax64(k1, k2));
#pragma unroll
                for (int off = 16; off > 0; off >>= 1)
                    m = umax64(m, __shfl_xor_sync(0xffffffffu, m, off));
                if (k0 == m) k0 = 0ull;
                else if (k1 == m) k1 = 0ull;
                else if (k2 == m) k2 = 0ull;
                if (lane == r) {
                    s_t[r] = __uint_as_float((unsigned)(m >> 13) - 1u);
                    s_i[r] = (NN - 1) - (int)(m & (u64)(NN - 1));
                }
            }
        }
    }
    __syncthreads();

    // Gather top predictions; c_k = 0.5*t_k - p_k.
    if (tid < KK) {
        float pk = pred_row[s_i[tid]];
        s_p[tid] = pk;
        s_c[tid] = 0.5f * s_t[tid] - pk;
    }
    __syncthreads();

    // ---------------- Phase B: A_k = sum_j |c_k + x_j|, Sx = sum_j x_j -------
    // relu(d) = 0.5*(d + |d|) exactly in fp32; sum_j relu(c_k+x_j)
    //   = 0.5*(NN*c_k + Sx + A_k).
    const u64 ABSMASK = 0x7fffffff7fffffffull;
    u64 c2[KK], a2[KK];
#pragma unroll
    for (int k = 0; k < KK; k++) { float c = s_c[k]; c2[k] = pack2(c, c); a2[k] = 0ull; }
    u64 sx2 = 0ull;

#pragma unroll
    for (int it = 0; it < ITERS; it++) {
        float4 p = p4[tid + it * THREADS];
        u64 x01 = pack2(p.x, p.y);
        u64 x23 = pack2(p.z, p.w);
        sx2 = add2(sx2, x01);
        sx2 = add2(sx2, x23);
#pragma unroll
        for (int k = 0; k < KK; k++) {
            u64 d0 = add2(c2[k], x01) & ABSMASK;
            a2[k] = add2(a2[k], d0);
            u64 d1 = add2(c2[k], x23) & ABSMASK;
            a2[k] = add2(a2[k], d1);
        }
    }

    float A[KK];
#pragma unroll
    for (int k = 0; k < KK; k++) A[k] = sum2(a2[k]);
    float sx = sum2(sx2);

#pragma unroll
    for (int k = 0; k < KK; k++) {
#pragma unroll
        for (int off = 16; off > 0; off >>= 1)
            A[k] += __shfl_xor_sync(0xffffffffu, A[k], off);
    }
#pragma unroll
    for (int off = 16; off > 0; off >>= 1)
        sx += __shfl_xor_sync(0xffffffffu, sx, off);

    if (lane == 0) {
#pragma unroll
        for (int k = 0; k < KK; k++) s_sums[warp][k] = A[k];
        s_sumx[warp] = sx;
    }
    __syncthreads();

    if (tid < KK) {
        const int k = tid;
        float Ak = 0.f, Sx = 0.f;
#pragma unroll
        for (int w = 0; w < NWARP; w++) { Ak += s_sums[w][k]; Sx += s_sumx[w]; }
        float ck = s_c[k];
        float S_full = 0.5f * (fmaf((float)NN, ck, Sx) + Ak);
        float sub = 0.f;
        for (int r = 0; r <= k; r++) sub += fmaxf(ck + s_p[r], 0.f);
        float per = (S_full - sub) / (float)(NN - k);
        s_loss[k] = (s_t[k] > 0.25f) ? per : 0.f;
    }
    __syncthreads();

    if (tid == 0) {
        float acc = 0.f;
#pragma unroll
        for (int k = 0; k < KK; k++) acc += s_loss[k];
        g_partial[row] = acc;
        __threadfence();
        unsigned t = atomicAdd(&g_ticket, 1u);
        s_last = (t == BB - 1);
    }
    __syncthreads();

    // Last block: deterministic reduction of all 1024 row partials.
    if (s_last) {
        __threadfence();
        float v = g_partial[tid] + g_partial[tid + 256] +
                  g_partial[tid + 512] + g_partial[tid + 768];
        __shared__ float sred[THREADS];
        sred[tid] = v;
        __syncthreads();
#pragma unroll
        for (int stride = THREADS / 2; stride > 0; stride >>= 1) {
            if (tid < stride) sred[tid] += sred[tid + stride];
            __syncthreads();
        }
        if (tid == 0) {
            out[0] = sred[0];
            g_ticket = 0;   // reset for next graph replay
        }
    }
}

extern "C" void kernel_launch(void* const* d_in, const int* in_sizes, int n_in,
                              void* d_out, int out_size) {
    const float* pred = (const float*)d_in[0];
    const float* targ = (const float*)d_in[1];
    vml_kernel<<<BB, THREADS>>>(pred, targ, (float*)d_out);
}